// round 5
// baseline (speedup 1.0000x reference)
#include <cuda_runtime.h>
#include <cuda_bf16.h>

// PLIF neuron scan, T=8. x: [B=32,T=8,S=131072] fp32 -> spikes same shape.
// Pure streaming, 268 MB total traffic, sustained-DRAM-bound (~5.8-6 TB/s
// measured plateau across MLP 8/16 and occ 26-84%).
//
// R5 lever: __ldlu (last-use) loads discard read lines from L2 immediately,
// dedicating L2 capacity to the dirty-write backlog -> longer same-direction
// DRAM write bursts, fewer rd/wr turnarounds.
//
// One thread = one float4 site; 8 timestep loads front-batched (MLP=8);
// spike stored immediately each step.

#define VTH 0.5f
#define S4C 32768u      // spatial float4 per (b,t) = 128*32*32/4
#define S4_SHIFT 15
#define S4_MASK 32767

__global__ __launch_bounds__(256) void plif_kernel(
    const float4* __restrict__ x,
    const float* __restrict__ w,
    float4* __restrict__ out)
{
    unsigned i = blockIdx.x * 256u + threadIdx.x;   // 0..1048575 exact
    unsigned b = i >> S4_SHIFT;
    unsigned s = i & S4_MASK;

    float wv = __ldg(w);
    float tau = 1.0f / (1.0f + __expf(-wv));

    unsigned base = (b << 3) * S4C + s;             // (b, t=0, s)
    const float4* px = x + base;
    float4* po = out + base;

    // Front-batch all 8 timestep loads (independent of the scan) -> MLP=8.
    // .lu: last-use, line dropped from cache after read.
    float4 xv[8];
#pragma unroll
    for (int t = 0; t < 8; t++) {
        xv[t] = __ldlu(px + t * S4C);
    }

    // Sequential membrane scan; store each spike vector immediately.
    float4 m = make_float4(0.f, 0.f, 0.f, 0.f);
#pragma unroll
    for (int t = 0; t < 8; t++) {
        float4 r;

        m.x = fmaf(tau, m.x, xv[t].x);
        r.x = (m.x > VTH) ? 1.0f : 0.0f;
        m.x = (m.x > VTH) ? 0.0f : m.x;

        m.y = fmaf(tau, m.y, xv[t].y);
        r.y = (m.y > VTH) ? 1.0f : 0.0f;
        m.y = (m.y > VTH) ? 0.0f : m.y;

        m.z = fmaf(tau, m.z, xv[t].z);
        r.z = (m.z > VTH) ? 1.0f : 0.0f;
        m.z = (m.z > VTH) ? 0.0f : m.z;

        m.w = fmaf(tau, m.w, xv[t].w);
        r.w = (m.w > VTH) ? 1.0f : 0.0f;
        m.w = (m.w > VTH) ? 0.0f : m.w;

        __stcs(po + t * S4C, r);
    }
}

extern "C" void kernel_launch(void* const* d_in, const int* in_sizes, int n_in,
                              void* d_out, int out_size) {
    const float4* x = (const float4*)d_in[0];
    const float* w = (const float*)d_in[1];
    float4* o = (float4*)d_out;

    // 1,048,576 float4 sites -> exact 4096 x 256 grid
    plif_kernel<<<4096, 256>>>(x, w, o);
}

// round 6
// speedup vs baseline: 1.0028x; 1.0028x over previous
#include <cuda_runtime.h>
#include <cuda_bf16.h>

// PLIF neuron scan, T=8. x: [B=32,T=8,S=131072] fp32 -> spikes same shape.
// Pure streaming, 268 MB mandatory DRAM traffic per call. Sustained
// mixed-read/write DRAM rate is the binding constraint (confirmed across
// MLP 8/16, occ 26-84%, __ldcs/__ldlu: all ~5.7-5.9 TB/s).
//
// R6 lever: __stwt write-through stores. Avoids the 126 MB dirty-L2 backlog
// whose demand-eviction collides with the next replay's read stream;
// exposes both streams to the memory controller concurrently.

#define VTH 0.5f
#define S4C 32768u      // spatial float4 per (b,t) = 128*32*32/4
#define S4_SHIFT 15
#define S4_MASK 32767

__global__ __launch_bounds__(256) void plif_kernel(
    const float4* __restrict__ x,
    const float* __restrict__ w,
    float4* __restrict__ out)
{
    unsigned i = blockIdx.x * 256u + threadIdx.x;   // 0..1048575 exact
    unsigned b = i >> S4_SHIFT;
    unsigned s = i & S4_MASK;

    float wv = __ldg(w);
    float tau = 1.0f / (1.0f + __expf(-wv));

    unsigned base = (b << 3) * S4C + s;             // (b, t=0, s)
    const float4* px = x + base;
    float4* po = out + base;

    // Front-batch all 8 timestep loads (independent of the scan) -> MLP=8.
    float4 xv[8];
#pragma unroll
    for (int t = 0; t < 8; t++) {
        xv[t] = __ldcs(px + t * S4C);
    }

    // Sequential membrane scan; write-through each spike vector immediately.
    float4 m = make_float4(0.f, 0.f, 0.f, 0.f);
#pragma unroll
    for (int t = 0; t < 8; t++) {
        float4 r;

        m.x = fmaf(tau, m.x, xv[t].x);
        r.x = (m.x > VTH) ? 1.0f : 0.0f;
        m.x = (m.x > VTH) ? 0.0f : m.x;

        m.y = fmaf(tau, m.y, xv[t].y);
        r.y = (m.y > VTH) ? 1.0f : 0.0f;
        m.y = (m.y > VTH) ? 0.0f : m.y;

        m.z = fmaf(tau, m.z, xv[t].z);
        r.z = (m.z > VTH) ? 1.0f : 0.0f;
        m.z = (m.z > VTH) ? 0.0f : m.z;

        m.w = fmaf(tau, m.w, xv[t].w);
        r.w = (m.w > VTH) ? 1.0f : 0.0f;
        m.w = (m.w > VTH) ? 0.0f : m.w;

        __stwt(po + t * S4C, r);
    }
}

extern "C" void kernel_launch(void* const* d_in, const int* in_sizes, int n_in,
                              void* d_out, int out_size) {
    const float4* x = (const float4*)d_in[0];
    const float* w = (const float*)d_in[1];
    float4* o = (float4*)d_out;

    // 1,048,576 float4 sites -> exact 4096 x 256 grid
    plif_kernel<<<4096, 256>>>(x, w, o);
}